// round 2
// baseline (speedup 1.0000x reference)
#include <cuda_runtime.h>
#include <cstdint>

// Problem constants (fixed by the reference setup_inputs):
//   source: (N=4, C=256, H=200, W=304) fp32
//   rois:   (M=1024, 5) fp32   [bidx, x1, y1, x2, y2]
//   out:    (M, C, 14, 14) fp32
#define OUT_H 14
#define OUT_W 14
#define OHW   (OUT_H * OUT_W)      // 196
#define C_    256
#define H_    200
#define W_    304
#define HW_   (H_ * W_)
#define MAXM  4096
#define CCHUNK 64                  // channels per block (C_/CCHUNK blocks in y)

// KEEP_AR with AR = OUT_W/OUT_H = 1.0 ; EXTEND_RATIO = 0.1

// Scratch tables (allocation-free: __device__ globals)
__device__ int   g_base [MAXM];           // b * C*H*W
__device__ int   g_yoff0[MAXM * OUT_H];   // y0 * W
__device__ int   g_yoff1[MAXM * OUT_H];   // min(y0+1, H-1) * W
__device__ float g_wy   [MAXM * OUT_H];
__device__ int   g_x0   [MAXM * OUT_W];
__device__ int   g_x1   [MAXM * OUT_W];
__device__ float g_wx   [MAXM * OUT_W];

__global__ void roi_prep_kernel(const float* __restrict__ rois, int M) {
    int m = blockIdx.x * blockDim.x + threadIdx.x;
    if (m >= M) return;

    float b  = rois[m * 5 + 0];
    float x1 = rois[m * 5 + 1];
    float y1 = rois[m * 5 + 2];
    float x2 = rois[m * 5 + 3];
    float y2 = rois[m * 5 + 4];

    // KEEP_AR (AR = 1): grow the short side symmetrically
    float h  = y2 - y1 + 1.0f;
    float w  = x2 - x1 + 1.0f;
    float ew = (h - w) * 0.5f;   // (h*AR - w)/2
    float eh = (w - h) * 0.5f;   // (w/AR - h)/2
    if (ew > 0.0f) { x1 -= ew; x2 += ew; }
    else           { y1 -= eh; y2 += eh; }

    // EXTEND_RATIO = 0.1 -> pad each side by size * 0.05
    float sw = x2 - x1 + 1.0f;
    float sh = y2 - y1 + 1.0f;
    float dx = sw * 0.05f;
    float dy = sh * 0.05f;
    x1 -= dx; x2 += dx;
    y1 -= dy; y2 += dy;

    g_base[m] = (int)b * (C_ * HW_);

    float dyr = y2 - y1;
    float dxr = x2 - x1;

    #pragma unroll
    for (int i = 0; i < OUT_H; i++) {
        float t  = (float)i / (float)(OUT_H - 1);
        float ys = fminf(fmaxf(y1 + dyr * t, 0.0f), (float)(H_ - 1));
        float yf = floorf(ys);
        int   y0 = (int)yf;
        g_yoff0[m * OUT_H + i] = y0 * W_;
        g_yoff1[m * OUT_H + i] = min(y0 + 1, H_ - 1) * W_;
        g_wy   [m * OUT_H + i] = ys - yf;
    }
    #pragma unroll
    for (int i = 0; i < OUT_W; i++) {
        float t  = (float)i / (float)(OUT_W - 1);
        float xs = fminf(fmaxf(x1 + dxr * t, 0.0f), (float)(W_ - 1));
        float xf = floorf(xs);
        int   x0 = (int)xf;
        g_x0[m * OUT_W + i] = x0;
        g_x1[m * OUT_W + i] = min(x0 + 1, W_ - 1);
        g_wx[m * OUT_W + i] = xs - xf;
    }
}

// One block = (roi m, chunk of CCHUNK channels). One thread = one (oy,ox).
// Spatial offsets/weights computed ONCE per thread, amortized over the c loop.
__global__ __launch_bounds__(OHW)
void roi_crop_kernel(const float* __restrict__ src, float* __restrict__ out) {
    int m  = blockIdx.x;
    int c0 = blockIdx.y * CCHUNK;
    int t  = threadIdx.x;           // 0..195
    int oy = t / OUT_W;
    int ox = t - oy * OUT_W;

    int   yo0 = g_yoff0[m * OUT_H + oy];
    int   yo1 = g_yoff1[m * OUT_H + oy];
    float wy  = g_wy   [m * OUT_H + oy];
    int   x0  = g_x0   [m * OUT_W + ox];
    int   x1  = g_x1   [m * OUT_W + ox];
    float wx  = g_wx   [m * OUT_W + ox];

    int off00 = yo0 + x0;
    int off01 = yo0 + x1;
    int off10 = yo1 + x0;
    int off11 = yo1 + x1;

    const float* __restrict__ p = src + g_base[m] + c0 * HW_;
    float* __restrict__ q = out + (m * C_ + c0) * OHW + t;

    #pragma unroll 4
    for (int c = 0; c < CCHUNK; c++) {
        float v00 = __ldg(p + off00);
        float v01 = __ldg(p + off01);
        float v10 = __ldg(p + off10);
        float v11 = __ldg(p + off11);

        float top = fmaf(wx, v01 - v00, v00);
        float bot = fmaf(wx, v11 - v10, v10);
        *q = fmaf(wy, bot - top, top);

        p += HW_;
        q += OHW;
    }
}

extern "C" void kernel_launch(void* const* d_in, const int* in_sizes, int n_in,
                              void* d_out, int out_size) {
    const float* src  = (const float*)d_in[0];
    const float* rois = (const float*)d_in[1];
    float*       out  = (float*)d_out;

    int M = in_sizes[1] / 5;              // 1024

    roi_prep_kernel<<<(M + 127) / 128, 128>>>(rois, M);

    dim3 grid(M, C_ / CCHUNK);
    roi_crop_kernel<<<grid, OHW>>>(src, out);
}

// round 3
// speedup vs baseline: 1.0002x; 1.0002x over previous
#include <cuda_runtime.h>
#include <cstdint>

// Problem constants (fixed by the reference setup_inputs):
//   source: (N=4, C=256, H=200, W=304) fp32
//   rois:   (M=1024, 5) fp32   [bidx, x1, y1, x2, y2]
//   out:    (M, C, 14, 14) fp32
#define OUT_H 14
#define OUT_W 14
#define OHW   (OUT_H * OUT_W)      // 196
#define C_    256
#define H_    200
#define W_    304
#define HW_   (H_ * W_)
#define MAXM  4096
#define CCHUNK 64                  // channels per block (C_/CCHUNK blocks in y)

// KEEP_AR with AR = OUT_W/OUT_H = 1.0 ; EXTEND_RATIO = 0.1

// Scratch tables (allocation-free: __device__ globals)
__device__ int   g_base [MAXM];           // b * C*H*W
__device__ int   g_yoff0[MAXM * OUT_H];   // y0 * W
__device__ int   g_yoff1[MAXM * OUT_H];   // min(y0+1, H-1) * W
__device__ float g_wy   [MAXM * OUT_H];
__device__ int   g_x0   [MAXM * OUT_W];
__device__ int   g_x1   [MAXM * OUT_W];
__device__ float g_wx   [MAXM * OUT_W];

__global__ void roi_prep_kernel(const float* __restrict__ rois, int M) {
    int m = blockIdx.x * blockDim.x + threadIdx.x;
    if (m >= M) return;

    float b  = rois[m * 5 + 0];
    float x1 = rois[m * 5 + 1];
    float y1 = rois[m * 5 + 2];
    float x2 = rois[m * 5 + 3];
    float y2 = rois[m * 5 + 4];

    // KEEP_AR (AR = 1): grow the short side symmetrically
    float h  = y2 - y1 + 1.0f;
    float w  = x2 - x1 + 1.0f;
    float ew = (h - w) * 0.5f;   // (h*AR - w)/2
    float eh = (w - h) * 0.5f;   // (w/AR - h)/2
    if (ew > 0.0f) { x1 -= ew; x2 += ew; }
    else           { y1 -= eh; y2 += eh; }

    // EXTEND_RATIO = 0.1 -> pad each side by size * 0.05
    float sw = x2 - x1 + 1.0f;
    float sh = y2 - y1 + 1.0f;
    float dx = sw * 0.05f;
    float dy = sh * 0.05f;
    x1 -= dx; x2 += dx;
    y1 -= dy; y2 += dy;

    g_base[m] = (int)b * (C_ * HW_);

    float dyr = y2 - y1;
    float dxr = x2 - x1;

    #pragma unroll
    for (int i = 0; i < OUT_H; i++) {
        float t  = (float)i / (float)(OUT_H - 1);
        float ys = fminf(fmaxf(y1 + dyr * t, 0.0f), (float)(H_ - 1));
        float yf = floorf(ys);
        int   y0 = (int)yf;
        g_yoff0[m * OUT_H + i] = y0 * W_;
        g_yoff1[m * OUT_H + i] = min(y0 + 1, H_ - 1) * W_;
        g_wy   [m * OUT_H + i] = ys - yf;
    }
    #pragma unroll
    for (int i = 0; i < OUT_W; i++) {
        float t  = (float)i / (float)(OUT_W - 1);
        float xs = fminf(fmaxf(x1 + dxr * t, 0.0f), (float)(W_ - 1));
        float xf = floorf(xs);
        int   x0 = (int)xf;
        g_x0[m * OUT_W + i] = x0;
        g_x1[m * OUT_W + i] = min(x0 + 1, W_ - 1);
        g_wx[m * OUT_W + i] = xs - xf;
    }
}

// One block = (roi m, chunk of CCHUNK channels). One thread = one (oy,ox).
// Spatial offsets/weights computed ONCE per thread, amortized over the c loop.
__global__ __launch_bounds__(OHW)
void roi_crop_kernel(const float* __restrict__ src, float* __restrict__ out) {
    int m  = blockIdx.x;
    int c0 = blockIdx.y * CCHUNK;
    int t  = threadIdx.x;           // 0..195
    int oy = t / OUT_W;
    int ox = t - oy * OUT_W;

    int   yo0 = g_yoff0[m * OUT_H + oy];
    int   yo1 = g_yoff1[m * OUT_H + oy];
    float wy  = g_wy   [m * OUT_H + oy];
    int   x0  = g_x0   [m * OUT_W + ox];
    int   x1  = g_x1   [m * OUT_W + ox];
    float wx  = g_wx   [m * OUT_W + ox];

    int off00 = yo0 + x0;
    int off01 = yo0 + x1;
    int off10 = yo1 + x0;
    int off11 = yo1 + x1;

    const float* __restrict__ p = src + g_base[m] + c0 * HW_;
    float* __restrict__ q = out + (m * C_ + c0) * OHW + t;

    #pragma unroll 4
    for (int c = 0; c < CCHUNK; c++) {
        float v00 = __ldg(p + off00);
        float v01 = __ldg(p + off01);
        float v10 = __ldg(p + off10);
        float v11 = __ldg(p + off11);

        float top = fmaf(wx, v01 - v00, v00);
        float bot = fmaf(wx, v11 - v10, v10);
        *q = fmaf(wy, bot - top, top);

        p += HW_;
        q += OHW;
    }
}

extern "C" void kernel_launch(void* const* d_in, const int* in_sizes, int n_in,
                              void* d_out, int out_size) {
    const float* src  = (const float*)d_in[0];
    const float* rois = (const float*)d_in[1];
    float*       out  = (float*)d_out;

    int M = in_sizes[1] / 5;              // 1024

    roi_prep_kernel<<<(M + 127) / 128, 128>>>(rois, M);

    dim3 grid(M, C_ / CCHUNK);
    roi_crop_kernel<<<grid, OHW>>>(src, out);
}